// round 15
// baseline (speedup 1.0000x reference)
#include <cuda_runtime.h>
#include <stdint.h>

#define N_HITS  8192
#define E_MAXSZ 8192
#define ROW_CAP 64
#define LIST_CAP 64
#define NBLK 512            // pipeline blocks
#define NZB  64             // dedicated zeroer blocks
#define NTOT (NBLK + NZB)   // 576 <= 592 wave-1 slots (4/SM * 148)
#define ROWS_PER_BLK 16     // 512 * 16 = 8192
#define NZROW (2 * N_HITS)  // 16384 matrix rows to zero
#define ZCHUNK 4            // rows per work-steal grab (128 KB)

// Output layout (float32 elements), tuple flattened in order:
// X (8192x3), Ri (8192x8192), Ro (8192x8192), y (8192), edges (8192x2), edge_mask (8192)
#define OFF_X     ((size_t)0)
#define OFF_RI    ((size_t)24576)
#define OFF_RO    (OFF_RI + (size_t)N_HITS * (size_t)E_MAXSZ)
#define OFF_Y     (OFF_RO + (size_t)N_HITS * (size_t)E_MAXSZ)
#define OFF_EDGES (OFF_Y + (size_t)E_MAXSZ)
#define OFF_MASK  (OFF_EDGES + (size_t)2 * E_MAXSZ)

// NOTE: Ri and Ro are contiguous: zero region = [OFF_RI, OFF_RI + NZROW*E_MAXSZ)

// ---- scratch (device globals; zero-initialized at module load) ----
__device__ float  g_phin[N_HITS];
__device__ float  g_zn[N_HITS];
__device__ float  g_track[N_HITS];
__device__ int    g_trkInt[N_HITS];
__device__ float  g_ev[N_HITS];
__device__ int    g_st[N_HITS];

__device__ int    g_stcnt[32];              // reset by block 0 after final barrier
__device__ float4 g_stdata[32][N_HITS];     // {phin, zn, idx_bits, ev}

__device__ int    g_blockSum[NBLK];

// per-track edge lists (counters reset in pipeline phase 0 each run)
__device__ int    g_inCnt[1024];            // edges e with track[dst[e]] == t  -> Ri rows
__device__ int    g_outCnt[1024];           // edges e with track[src[e]] == t  -> Ro rows
__device__ int    g_inList[1024][LIST_CAP];
__device__ int    g_outList[1024][LIST_CAP];

// work-steal + barrier counters (reset by block 0 after final barrier)
__device__ int    g_zCtr;                   // next zero-chunk to grab
__device__ int    g_barA;                   // pipeline barrier 1 (512)
__device__ int    g_barB;                   // pipeline barrier 2 (512)
__device__ int    g_barZ;                   // all-zeros+emit barrier (576)
__device__ int    g_barS;                   // post-scatter barrier (576)

// ---------------------------------------------------------------------------
// grid-wide barrier for n co-resident blocks (all blocks here are wave-1
// resident by __launch_bounds__(256,4): 592 slots >= NTOT, in-order dispatch)
// ---------------------------------------------------------------------------
__device__ __forceinline__ void grid_bar(int* ctr, int n) {
    __syncthreads();
    if (threadIdx.x == 0) {
        __threadfence();                       // release
        atomicAdd(ctr, 1);
        while (*(volatile int*)ctr < n) { __nanosleep(128); }
        __threadfence();                       // acquire
    }
    __syncthreads();
}

// ---------------------------------------------------------------------------
// persistent zero loop: steal ZCHUNK-row chunks until the region is done.
// No fences inside the loop — stores stream freely.
// ---------------------------------------------------------------------------
__device__ __forceinline__ void zero_loop(float* __restrict__ out,
                                          int* s_grab, int tid) {
    const float4 z4 = make_float4(0.f, 0.f, 0.f, 0.f);
    for (;;) {
        __syncthreads();
        if (tid == 0) *s_grab = atomicAdd(&g_zCtr, ZCHUNK);
        __syncthreads();
        int r0 = *s_grab;
        if (r0 >= NZROW) break;
        int r1 = r0 + ZCHUNK; if (r1 > NZROW) r1 = NZROW;
        for (int r = r0; r < r1; r++) {
            float4* p = (float4*)(out + OFF_RI + (size_t)r * E_MAXSZ);
            #pragma unroll
            for (int k = 0; k < 8; k++)
                p[k * 256 + tid] = z4;
        }
    }
}

// scatter the ones for one (matrix,row) pair, lane-strided within a warp
__device__ __forceinline__ void scatter_row(float* __restrict__ out, int mrow,
                                            int lane) {
    int mat = mrow >> 13;                 // 0 = Ri, 1 = Ro
    int row = mrow & (N_HITS - 1);
    size_t base = (mat == 0 ? OFF_RI : OFF_RO) + (size_t)row * E_MAXSZ;
    int t = g_trkInt[row];
    int c;
    const int* lst;
    if (mat == 0) { c = g_inCnt[t];  lst = g_inList[t];  }
    else          { c = g_outCnt[t]; lst = g_outList[t]; }
    if (c > LIST_CAP) c = LIST_CAP;
    for (int m = lane; m < c; m += 32)
        out[base + (size_t)lst[m]] = 1.0f;
}

// ---------------------------------------------------------------------------
// Single persistent kernel, all 576 blocks wave-1 resident.
//   bids [0, NBLK)      : pipeline (prep -> pairs -> scan+emit), then join
//                         the zero loop.
//   bids [NBLK, NTOT)   : zero loop from t=0.
// All blocks: grid barrier (zeros + emit complete) -> scatter -> barrier ->
//             block 0 resets state for the next graph replay.
// ---------------------------------------------------------------------------
__global__ void __launch_bounds__(256, 4) k_mega(const float* __restrict__ ed,
                                                 float* __restrict__ out) {
    __shared__ int s_rowj[ROWS_PER_BLK][ROW_CAP];   // 4 KB
    __shared__ int s_rowcnt[ROWS_PER_BLK];
    __shared__ int s_bs[NBLK];                      // 2 KB
    __shared__ int s_pfx[256];                      // 1 KB
    __shared__ int s_wt[8];
    __shared__ int s_count;
    __shared__ int s_grab;

    int tid  = threadIdx.x;
    int bid  = blockIdx.x;
    int lane = tid & 31;
    int wid  = tid >> 5;

    if (bid < NBLK) {
        // ===== Phase 0: prep (this block's 16 hits) + counter reset =====
        if (tid < ROWS_PER_BLK) {
            int i = bid * ROWS_PER_BLK + tid;

            float ev  = ed[6 * i + 0];
            float x   = ed[6 * i + 1];
            float y   = ed[6 * i + 2];
            float z   = ed[6 * i + 3];
            float stf = ed[6 * i + 4];
            float trk = ed[6 * i + 5];

            // IEEE-exact f32 path (no fma contraction, rn division/sqrt)
            float xx = __fmul_rn(x, x);
            float yy = __fmul_rn(y, y);
            float r  = __fsqrt_rn(__fadd_rn(xx, yy));
            float phi = atan2f(x, y);

            float rn   = __fadd_rn(__fdiv_rn(__fmul_rn(2.0f, __fadd_rn(r,  -269.0f)),  312.0f), -1.0f);
            float phin = __fadd_rn(__fdiv_rn(__fmul_rn(2.0f, __fadd_rn(phi,  3.15f)),    6.3f), -1.0f);
            float zn   = __fadd_rn(__fdiv_rn(__fmul_rn(2.0f, __fadd_rn(z,  2386.0f)),  4772.0f), -1.0f);

            out[OFF_X + 3 * (size_t)i + 0] = rn;
            out[OFF_X + 3 * (size_t)i + 1] = phin;
            out[OFF_X + 3 * (size_t)i + 2] = zn;

            g_phin[i]   = phin;
            g_zn[i]     = zn;
            g_track[i]  = trk;
            g_trkInt[i] = (int)trk;
            g_ev[i]     = ev;
            int st      = (int)stf;
            g_st[i]     = st;

            if (st >= 0 && st < 32) {
                int slot = atomicAdd(&g_stcnt[st], 1);
                float4 d;
                d.x = phin; d.y = zn; d.z = __int_as_float(i); d.w = ev;
                g_stdata[st][slot] = d;
            }
        }
        if (tid < 2) { g_inCnt[bid * 2 + tid] = 0; g_outCnt[bid * 2 + tid] = 0; }

        grid_bar(&g_barA, NBLK);

        // ===== Phase 1: pairs — warp w handles local rows w and w+8 =====
        #pragma unroll
        for (int half = 0; half < 2; half++) {
            int local = wid + half * 8;
            int row   = bid * ROWS_PER_BLK + local;

            int myMatch[16];
            int mycnt = 0;

            int s2 = g_st[row] + 1;
            if (s2 >= 0 && s2 < 32) {
                int n2 = g_stcnt[s2];
                float pi  = g_phin[row];
                float zi  = g_zn[row];
                float evi = g_ev[row];
                for (int k = lane; k < n2; k += 32) {
                    float4 c = g_stdata[s2][k];
                    float dphi = c.x - pi;
                    float dz   = c.y - zi;
                    bool ok = (c.w == evi) &
                              (dphi > -0.04f) & (dphi < 0.04f) &
                              (dz   > -0.03f) & (dz   < 0.03f);
                    if (ok && mycnt < 16) myMatch[mycnt++] = __float_as_int(c.z);
                }
            }

            // warp exclusive scan of per-lane counts
            int off = mycnt;
            #pragma unroll
            for (int d = 1; d < 32; d <<= 1) {
                int v = __shfl_up_sync(0xFFFFFFFFu, off, d);
                if (lane >= d) off += v;
            }
            int total = __shfl_sync(0xFFFFFFFFu, off, 31);
            int excl  = off - mycnt;
            for (int m = 0; m < mycnt; m++) {
                int e = excl + m;
                if (e < ROW_CAP) s_rowj[local][e] = myMatch[m];
            }
            __syncwarp();

            if (lane == 0) {
                int cnt = total < ROW_CAP ? total : ROW_CAP;
                // insertion sort ascending by j (restores exact nonzero order)
                for (int a = 1; a < cnt; a++) {
                    int v = s_rowj[local][a];
                    int b = a - 1;
                    while (b >= 0 && s_rowj[local][b] > v) { s_rowj[local][b + 1] = s_rowj[local][b]; b--; }
                    s_rowj[local][b + 1] = v;
                }
                s_rowcnt[local] = cnt;
            }
            __syncwarp();
        }

        __syncthreads();
        if (tid == 0) {
            int sum = 0;
            #pragma unroll
            for (int m = 0; m < ROWS_PER_BLK; m++) sum += s_rowcnt[m];
            g_blockSum[bid] = sum;
        }

        grid_bar(&g_barB, NBLK);

        // ===== Phase 2: decoupled scan of block sums, then emit =====
        s_bs[tid]       = g_blockSum[tid];
        s_bs[tid + 256] = g_blockSum[tid + 256];
        __syncthreads();

        int pairSum = s_bs[2 * tid] + s_bs[2 * tid + 1];
        int inc = pairSum;
        #pragma unroll
        for (int d = 1; d < 32; d <<= 1) {
            int v = __shfl_up_sync(0xFFFFFFFFu, inc, d);
            if (lane >= d) inc += v;
        }
        if (lane == 31) s_wt[wid] = inc;
        __syncthreads();
        if (wid == 0 && lane < 8) {
            int w = s_wt[lane];
            int wi = w;
            #pragma unroll
            for (int d = 1; d < 8; d <<= 1) {
                int v = __shfl_up_sync(0xFFu, wi, d);
                if (lane >= d) wi += v;
            }
            s_wt[lane] = wi - w;
            if (lane == 7) s_count = wi;
        }
        __syncthreads();
        int pairExcl = inc - pairSum + s_wt[wid];
        s_pfx[tid] = pairExcl;
        __syncthreads();

        int count   = s_count;
        int blkBase = s_pfx[bid >> 1] + ((bid & 1) ? s_bs[bid - 1] : 0);

        // emit: warp w handles local rows w and w+8
        #pragma unroll
        for (int half = 0; half < 2; half++) {
            int local = wid + half * 8;
            int row   = bid * ROWS_PER_BLK + local;
            int cnt   = s_rowcnt[local];

            int off = blkBase;
            for (int m = 0; m < local; m++) off += s_rowcnt[m];

            float ti = g_track[row];
            int  tsI = g_trkInt[row];

            for (int q = lane; q < cnt; q += 32) {
                int e = off + q;
                if (e < E_MAXSZ) {
                    int j = s_rowj[local][q];
                    out[OFF_EDGES + 2 * (size_t)e + 0] = ti;
                    out[OFF_EDGES + 2 * (size_t)e + 1] = g_track[j];
                    int tdI = g_trkInt[j];
                    int so = atomicAdd(&g_outCnt[tsI], 1);
                    if (so < LIST_CAP) g_outList[tsI][so] = e;
                    int si = atomicAdd(&g_inCnt[tdI], 1);
                    if (si < LIST_CAP) g_inList[tdI][si] = e;
                }
            }
        }

        // slot bookkeeping: y, mask, fill (nonzero fill_value=0 -> track[0])
        if (tid < ROWS_PER_BLK) {
            int s = bid * ROWS_PER_BLK + tid;
            out[OFF_Y + (size_t)s] = 0.0f;
            out[OFF_MASK + (size_t)s] = (s < count) ? 1.0f : 0.0f;
            if (s >= count) {
                float t0 = g_track[0];
                out[OFF_EDGES + 2 * (size_t)s + 0] = t0;
                out[OFF_EDGES + 2 * (size_t)s + 1] = t0;
            }
        }
        // pipeline done -> join the zero loop (stay resident, keep storing)
    }

    // ===== persistent zeroing (all blocks; zeroers from t=0) =====
    zero_loop(out, &s_grab, tid);

    // ===== all zeros stored + all emit done (pipeline blocks only reach
    //       here after emit). Barrier orders both for everyone. =====
    grid_bar(&g_barZ, NTOT);

    // ===== scatter ones: global warp gw covers rows gw, gw+4608, ... =====
    int gw = bid * 8 + wid;                  // 0 .. 4607
    #pragma unroll
    for (int k = 0; k < 4; k++) {
        int mrow = gw + k * (NTOT * 8);
        if (mrow < NZROW) scatter_row(out, mrow, lane);
    }

    // ===== final barrier; block 0 resets state for the next replay =====
    __syncthreads();
    if (tid == 0) {
        __threadfence();
        atomicAdd(&g_barS, 1);
        if (bid == 0) {
            while (*(volatile int*)&g_barS < NTOT) { __nanosleep(128); }
            __threadfence();
            for (int m = 0; m < 32; m++) g_stcnt[m] = 0;
            g_zCtr = 0;
            g_barA = 0; g_barB = 0; g_barZ = 0; g_barS = 0;
            __threadfence();
        }
    }
}

// ---------------------------------------------------------------------------
extern "C" void kernel_launch(void* const* d_in, const int* in_sizes, int n_in,
                              void* d_out, int out_size) {
    const float* ed = (const float*)d_in[0];
    float* out = (float*)d_out;

    k_mega<<<NTOT, 256>>>(ed, out);
}

// round 16
// speedup vs baseline: 1.2485x; 1.2485x over previous
#include <cuda_runtime.h>
#include <stdint.h>

#define N_HITS  8192
#define E_MAXSZ 8192
#define ROW_CAP 64
#define LIST_CAP 64
#define NBLK 512
#define ROWS_PER_BLK 16     // 512 * 16 = 8192

// Output layout (float32 elements), tuple flattened in order:
// X (8192x3), Ri (8192x8192), Ro (8192x8192), y (8192), edges (8192x2), edge_mask (8192)
#define OFF_X     ((size_t)0)
#define OFF_RI    ((size_t)24576)
#define OFF_RO    (OFF_RI + (size_t)N_HITS * (size_t)E_MAXSZ)
#define OFF_Y     (OFF_RO + (size_t)N_HITS * (size_t)E_MAXSZ)
#define OFF_EDGES (OFF_Y + (size_t)E_MAXSZ)
#define OFF_MASK  (OFF_EDGES + (size_t)2 * E_MAXSZ)

// ---- scratch (device globals; zero-initialized at module load) ----
__device__ float  g_phin[N_HITS];
__device__ float  g_zn[N_HITS];
__device__ float  g_track[N_HITS];
__device__ int    g_trkInt[N_HITS];
__device__ float  g_ev[N_HITS];
__device__ int    g_st[N_HITS];

__device__ int    g_stcnt[32];              // reset in k_scatter (after last reader)
__device__ float4 g_stdata[32][N_HITS];     // {phin, zn, idx_bits, ev}

__device__ int    g_blockSum[NBLK];

// per-track edge lists (counters reset in pipeline phase 0 each run)
__device__ int    g_inCnt[1024];            // edges e with track[dst[e]] == t  -> Ri rows
__device__ int    g_outCnt[1024];           // edges e with track[src[e]] == t  -> Ro rows
__device__ int    g_inList[1024][LIST_CAP];
__device__ int    g_outList[1024][LIST_CAP];

// spin-barrier counters (reset in k_scatter for the next replay)
__device__ int    g_barA;
__device__ int    g_barB;

// ---------------------------------------------------------------------------
// grid-wide barrier for exactly NBLK co-resident pipeline blocks.
// Zero-role blocks never touch it; __launch_bounds__(256,4) gives 592 >= 512
// wave-1 slots so all participants are resident (in-order dispatch).
// ---------------------------------------------------------------------------
__device__ __forceinline__ void grid_bar(int* ctr) {
    __syncthreads();
    if (threadIdx.x == 0) {
        __threadfence();                       // release
        atomicAdd(ctr, 1);
        while (*(volatile int*)ctr < NBLK) { __nanosleep(64); }
        __threadfence();                       // acquire
    }
    __syncthreads();
}

// ---------------------------------------------------------------------------
// K1: mega kernel (R9 topology — proven best).
//   bids [0, NBLK)          : pipeline (prep -> pairs -> scan+emit), retire.
//   bids [NBLK, NBLK+16384) : zero one Ri/Ro row with STREAMING stores (.cs
//                             — no reuse, evict early) and retire. No fences,
//                             no shared-state handshakes (R13/R14 lessons).
// ---------------------------------------------------------------------------
__global__ void __launch_bounds__(256, 4) k_mega(const float* __restrict__ ed,
                                                 float* __restrict__ out) {
    __shared__ int s_rowj[ROWS_PER_BLK][ROW_CAP];   // 4 KB
    __shared__ int s_rowcnt[ROWS_PER_BLK];
    __shared__ int s_bs[NBLK];                      // 2 KB
    __shared__ int s_pfx[256];                      // 1 KB
    __shared__ int s_wt[8];
    __shared__ int s_count;

    int tid  = threadIdx.x;
    int bid  = blockIdx.x;

    // ===== zero role: bulk-zero one 8192-float row (streaming), retire ====
    if (bid >= NBLK) {
        int row = bid - NBLK;
        size_t base = (row < N_HITS)
            ? OFF_RI + (size_t)row * E_MAXSZ
            : OFF_RO + (size_t)(row - N_HITS) * E_MAXSZ;
        float4* p = (float4*)(out + base);
        const float4 z4 = make_float4(0.f, 0.f, 0.f, 0.f);
        #pragma unroll
        for (int k = 0; k < 8; k++)
            __stcs(p + k * 256 + tid, z4);
        return;
    }

    int lane = tid & 31;
    int wid  = tid >> 5;

    // ===== Phase 0: prep (this block's 16 hits) + counter reset =====
    if (tid < ROWS_PER_BLK) {
        int i = bid * ROWS_PER_BLK + tid;

        float ev  = ed[6 * i + 0];
        float x   = ed[6 * i + 1];
        float y   = ed[6 * i + 2];
        float z   = ed[6 * i + 3];
        float stf = ed[6 * i + 4];
        float trk = ed[6 * i + 5];

        // IEEE-exact f32 path (no fma contraction, rn division/sqrt)
        float xx = __fmul_rn(x, x);
        float yy = __fmul_rn(y, y);
        float r  = __fsqrt_rn(__fadd_rn(xx, yy));
        float phi = atan2f(x, y);

        float rn   = __fadd_rn(__fdiv_rn(__fmul_rn(2.0f, __fadd_rn(r,  -269.0f)),  312.0f), -1.0f);
        float phin = __fadd_rn(__fdiv_rn(__fmul_rn(2.0f, __fadd_rn(phi,  3.15f)),    6.3f), -1.0f);
        float zn   = __fadd_rn(__fdiv_rn(__fmul_rn(2.0f, __fadd_rn(z,  2386.0f)),  4772.0f), -1.0f);

        out[OFF_X + 3 * (size_t)i + 0] = rn;
        out[OFF_X + 3 * (size_t)i + 1] = phin;
        out[OFF_X + 3 * (size_t)i + 2] = zn;

        g_phin[i]   = phin;
        g_zn[i]     = zn;
        g_track[i]  = trk;
        g_trkInt[i] = (int)trk;
        g_ev[i]     = ev;
        int st      = (int)stf;
        g_st[i]     = st;

        if (st >= 0 && st < 32) {
            int slot = atomicAdd(&g_stcnt[st], 1);
            float4 d;
            d.x = phin; d.y = zn; d.z = __int_as_float(i); d.w = ev;
            g_stdata[st][slot] = d;
        }
    }
    if (tid < 2) { g_inCnt[bid * 2 + tid] = 0; g_outCnt[bid * 2 + tid] = 0; }

    grid_bar(&g_barA);

    // ===== Phase 1: pairs — warp w handles local rows w and w+8 =====
    #pragma unroll
    for (int half = 0; half < 2; half++) {
        int local = wid + half * 8;
        int row   = bid * ROWS_PER_BLK + local;

        int myMatch[16];
        int mycnt = 0;

        int s2 = g_st[row] + 1;
        if (s2 >= 0 && s2 < 32) {
            int n2 = g_stcnt[s2];
            float pi  = g_phin[row];
            float zi  = g_zn[row];
            float evi = g_ev[row];
            for (int k = lane; k < n2; k += 32) {
                float4 c = g_stdata[s2][k];
                float dphi = c.x - pi;
                float dz   = c.y - zi;
                bool ok = (c.w == evi) &
                          (dphi > -0.04f) & (dphi < 0.04f) &
                          (dz   > -0.03f) & (dz   < 0.03f);
                if (ok && mycnt < 16) myMatch[mycnt++] = __float_as_int(c.z);
            }
        }

        // warp exclusive scan of per-lane counts
        int off = mycnt;
        #pragma unroll
        for (int d = 1; d < 32; d <<= 1) {
            int v = __shfl_up_sync(0xFFFFFFFFu, off, d);
            if (lane >= d) off += v;
        }
        int total = __shfl_sync(0xFFFFFFFFu, off, 31);
        int excl  = off - mycnt;
        for (int m = 0; m < mycnt; m++) {
            int e = excl + m;
            if (e < ROW_CAP) s_rowj[local][e] = myMatch[m];
        }
        __syncwarp();

        if (lane == 0) {
            int cnt = total < ROW_CAP ? total : ROW_CAP;
            // insertion sort ascending by j (restores exact nonzero order)
            for (int a = 1; a < cnt; a++) {
                int v = s_rowj[local][a];
                int b = a - 1;
                while (b >= 0 && s_rowj[local][b] > v) { s_rowj[local][b + 1] = s_rowj[local][b]; b--; }
                s_rowj[local][b + 1] = v;
            }
            s_rowcnt[local] = cnt;
        }
        __syncwarp();
    }

    __syncthreads();
    if (tid == 0) {
        int sum = 0;
        #pragma unroll
        for (int m = 0; m < ROWS_PER_BLK; m++) sum += s_rowcnt[m];
        g_blockSum[bid] = sum;
    }

    grid_bar(&g_barB);

    // ===== Phase 2: decoupled scan of block sums, then emit =====
    s_bs[tid]       = g_blockSum[tid];
    s_bs[tid + 256] = g_blockSum[tid + 256];
    __syncthreads();

    int pairSum = s_bs[2 * tid] + s_bs[2 * tid + 1];
    int inc = pairSum;
    #pragma unroll
    for (int d = 1; d < 32; d <<= 1) {
        int v = __shfl_up_sync(0xFFFFFFFFu, inc, d);
        if (lane >= d) inc += v;
    }
    if (lane == 31) s_wt[wid] = inc;
    __syncthreads();
    if (wid == 0 && lane < 8) {
        int w = s_wt[lane];
        int wi = w;
        #pragma unroll
        for (int d = 1; d < 8; d <<= 1) {
            int v = __shfl_up_sync(0xFFu, wi, d);
            if (lane >= d) wi += v;
        }
        s_wt[lane] = wi - w;
        if (lane == 7) s_count = wi;
    }
    __syncthreads();
    int pairExcl = inc - pairSum + s_wt[wid];
    s_pfx[tid] = pairExcl;
    __syncthreads();

    int count   = s_count;
    int blkBase = s_pfx[bid >> 1] + ((bid & 1) ? s_bs[bid - 1] : 0);

    // emit: warp w handles local rows w and w+8
    #pragma unroll
    for (int half = 0; half < 2; half++) {
        int local = wid + half * 8;
        int row   = bid * ROWS_PER_BLK + local;
        int cnt   = s_rowcnt[local];

        int off = blkBase;
        for (int m = 0; m < local; m++) off += s_rowcnt[m];

        float ti = g_track[row];
        int  tsI = g_trkInt[row];

        for (int q = lane; q < cnt; q += 32) {
            int e = off + q;
            if (e < E_MAXSZ) {
                int j = s_rowj[local][q];
                out[OFF_EDGES + 2 * (size_t)e + 0] = ti;
                out[OFF_EDGES + 2 * (size_t)e + 1] = g_track[j];
                int tdI = g_trkInt[j];
                int so = atomicAdd(&g_outCnt[tsI], 1);
                if (so < LIST_CAP) g_outList[tsI][so] = e;
                int si = atomicAdd(&g_inCnt[tdI], 1);
                if (si < LIST_CAP) g_inList[tdI][si] = e;
            }
        }
    }

    // slot bookkeeping: y, mask, fill (nonzero fill_value=0 -> track[0])
    if (tid < ROWS_PER_BLK) {
        int s = bid * ROWS_PER_BLK + tid;
        out[OFF_Y + (size_t)s] = 0.0f;
        out[OFF_MASK + (size_t)s] = (s < count) ? 1.0f : 0.0f;
        if (s >= count) {
            float t0 = g_track[0];
            out[OFF_EDGES + 2 * (size_t)s + 0] = t0;
            out[OFF_EDGES + 2 * (size_t)s + 1] = t0;
        }
    }
}

// ---------------------------------------------------------------------------
// K2: scatter the ones into the (already zeroed) Ri/Ro rows.
// One warp per (matrix,row): 2048 blocks x 8 warps. Per-track COUNTS are
// staged in smem (coalesced bulk load overlapped with the trkInt load),
// cutting the per-warp dependent gmem chain from ~4 to ~2 latencies.
// Also resets g_stcnt + barrier counters for the next replay.
// ---------------------------------------------------------------------------
__global__ void __launch_bounds__(256) k_scatter(float* __restrict__ out) {
    __shared__ int s_in[1024];
    __shared__ int s_out[1024];

    int tid  = threadIdx.x;
    int bid  = blockIdx.x;
    int lane = tid & 31;
    int wid  = tid >> 5;

    // issue the row's trkInt load FIRST (independent of the staging loads)
    int mrow = bid * 8 + wid;               // 0 .. 16383
    int mat  = mrow >> 13;                  // 0 = Ri, 1 = Ro
    int row  = mrow & (N_HITS - 1);
    int t    = g_trkInt[row];               // long-scoreboard, overlaps below

    // stage all per-track counts (coalesced)
    #pragma unroll
    for (int k = 0; k < 4; k++) {
        int idx = k * 256 + tid;
        s_in[idx]  = g_inCnt[idx];
        s_out[idx] = g_outCnt[idx];
    }

    if (bid == 0) {
        if (tid < 32) g_stcnt[tid] = 0;
        if (tid == 32) g_barA = 0;
        if (tid == 33) g_barB = 0;
    }
    __syncthreads();

    int c = (mat == 0) ? s_in[t] : s_out[t];
    if (c > LIST_CAP) c = LIST_CAP;
    const int* lst = (mat == 0) ? g_inList[t] : g_outList[t];
    size_t base = (mat == 0 ? OFF_RI : OFF_RO) + (size_t)row * E_MAXSZ;
    for (int m = lane; m < c; m += 32)
        out[base + (size_t)lst[m]] = 1.0f;
}

// ---------------------------------------------------------------------------
extern "C" void kernel_launch(void* const* d_in, const int* in_sizes, int n_in,
                              void* d_out, int out_size) {
    const float* ed = (const float*)d_in[0];
    float* out = (float*)d_out;

    k_mega   <<<NBLK + 2 * N_HITS, 256>>>(ed, out);
    k_scatter<<<2048, 256>>>(out);
}